// round 2
// baseline (speedup 1.0000x reference)
#include <cuda_runtime.h>

#define NNODES 50000
#define NEDGES 800000
#define FDIM   128
#define F3     384
#define RBFN   20
#define RCUT   5.0f
#define PI_F   3.14159265358979f

// Scratch: per-node phi = (silu(ns@W1+b1))@W2 + b2, shape (N, 384)
__device__ float g_phi[(size_t)NNODES * F3];

// ---------------------------------------------------------------------------
// Kernel 1: out = concat(node_scalar, node_vector)  (scatter-adds land on top)
// ---------------------------------------------------------------------------
__global__ void init_out_kernel(const float4* __restrict__ ns,
                                const float4* __restrict__ nv,
                                float4* __restrict__ out) {
    int i = blockIdx.x * blockDim.x + threadIdx.x;
    const int NS4 = NNODES * FDIM / 4;          // 1,600,000
    const int NT4 = NS4 + NNODES * F3 / 4;      // 6,400,000
    if (i < NS4)       out[i] = ns[i];
    else if (i < NT4)  out[i] = nv[i - NS4];
}

// ---------------------------------------------------------------------------
// Kernel 2: per-node fused MLP.  128-row tile per block, 256 threads,
// 8x8 register micro-tile, operands in smem (Xs 64KB + Ws 64KB).
// ---------------------------------------------------------------------------
__device__ __forceinline__ void mm_tile_128(const float* __restrict__ Xs,
                                            const float* __restrict__ Ws,
                                            int r0, int tc, float acc[8][8]) {
    #pragma unroll 4
    for (int k = 0; k < 128; k++) {
        float a[8];
        #pragma unroll
        for (int i = 0; i < 8; i++) a[i] = Xs[(r0 + i) * 128 + k];
        float4 bA = ((const float4*)Ws)[k * 32 + tc * 2];
        float4 bB = ((const float4*)Ws)[k * 32 + tc * 2 + 1];
        float b[8] = {bA.x, bA.y, bA.z, bA.w, bB.x, bB.y, bB.z, bB.w};
        #pragma unroll
        for (int i = 0; i < 8; i++)
            #pragma unroll
            for (int j = 0; j < 8; j++)
                acc[i][j] = fmaf(a[i], b[j], acc[i][j]);
    }
}

__global__ __launch_bounds__(256) void phi_kernel(
        const float* __restrict__ X,
        const float* __restrict__ W1,
        const float* __restrict__ b1,
        const float* __restrict__ W2,
        const float* __restrict__ b2) {
    extern __shared__ float sm[];
    float* Xs = sm;            // 128x128 tile (X, later h)
    float* Ws = sm + 16384;    // 128x128 weight tile
    const int tid  = threadIdx.x;
    const int row0 = blockIdx.x * 128;

    {
        const float4* X4  = (const float4*)X;
        const float4* W14 = (const float4*)W1;
        float4* Xs4 = (float4*)Xs;
        float4* Ws4 = (float4*)Ws;
        #pragma unroll
        for (int t = 0; t < 16; t++) {
            int i = tid + t * 256;
            int r = i >> 5, c = i & 31;
            int gr = row0 + r;
            float4 v = make_float4(0.f, 0.f, 0.f, 0.f);
            if (gr < NNODES) v = X4[gr * 32 + c];
            Xs4[i] = v;
        }
        #pragma unroll
        for (int t = 0; t < 16; t++) {
            int i = tid + t * 256;
            Ws4[i] = W14[i];
        }
    }
    __syncthreads();

    const int tr = tid >> 4, tc = tid & 15;
    const int r0 = tr * 8,  c0 = tc * 8;

    // ---- stage 1: h = silu(X @ W1 + b1) ----
    float acc[8][8];
    #pragma unroll
    for (int i = 0; i < 8; i++)
        #pragma unroll
        for (int j = 0; j < 8; j++) acc[i][j] = 0.f;

    mm_tile_128(Xs, Ws, r0, tc, acc);
    __syncthreads();   // all reads of Xs (as X) done

    #pragma unroll
    for (int j = 0; j < 8; j++) {
        float bias = b1[c0 + j];
        #pragma unroll
        for (int i = 0; i < 8; i++) {
            float v = acc[i][j] + bias;
            Xs[(r0 + i) * 128 + c0 + j] = v / (1.f + __expf(-v));  // silu
        }
    }
    __syncthreads();   // h visible

    // ---- stage 2: phi = h @ W2 + b2, in 3 column chunks of 128 ----
    const float4* W24 = (const float4*)W2;
    for (int ch = 0; ch < 3; ch++) {
        {
            float4* Ws4 = (float4*)Ws;
            #pragma unroll
            for (int t = 0; t < 16; t++) {
                int i = tid + t * 256;
                int k = i >> 5, c = i & 31;
                Ws4[i] = W24[k * 96 + ch * 32 + c];   // W2 row stride 384
            }
        }
        __syncthreads();

        float acc2[8][8];
        #pragma unroll
        for (int i = 0; i < 8; i++)
            #pragma unroll
            for (int j = 0; j < 8; j++) acc2[i][j] = 0.f;

        mm_tile_128(Xs, Ws, r0, tc, acc2);

        float bb[8];
        #pragma unroll
        for (int j = 0; j < 8; j++) bb[j] = b2[ch * 128 + c0 + j];

        #pragma unroll
        for (int i = 0; i < 8; i++) {
            int gr = row0 + r0 + i;
            if (gr < NNODES) {
                float4 o0 = make_float4(acc2[i][0] + bb[0], acc2[i][1] + bb[1],
                                        acc2[i][2] + bb[2], acc2[i][3] + bb[3]);
                float4 o1 = make_float4(acc2[i][4] + bb[4], acc2[i][5] + bb[5],
                                        acc2[i][6] + bb[6], acc2[i][7] + bb[7]);
                float4* dst = (float4*)(g_phi + (size_t)gr * F3 + ch * 128 + c0);
                dst[0] = o0;
                dst[1] = o1;
            }
        }
        __syncthreads();   // Ws reads done before next chunk overwrites
    }
}

// ---------------------------------------------------------------------------
// Kernel 3: per-edge RBF + gather + scatter-add.  One warp per edge,
// 8 edges per warp.  Vector atomics (red.global.add.v4.f32).
// ---------------------------------------------------------------------------
__device__ __forceinline__ void red4(float* p, float4 v) {
    asm volatile("red.global.add.v4.f32 [%0], {%1, %2, %3, %4};"
                 :: "l"(p), "f"(v.x), "f"(v.y), "f"(v.z), "f"(v.w)
                 : "memory");
}

#define EPW 8   // edges per warp

__global__ __launch_bounds__(256) void edge_kernel(
        const int2*  __restrict__ eidx,
        const float* __restrict__ rvec,
        const float* __restrict__ Wr,
        const float* __restrict__ br,
        const float* __restrict__ nv,
        float* __restrict__ out) {
    __shared__ float sWr[RBFN * F3 + F3];
    const int tid = threadIdx.x;
    for (int i = tid; i < RBFN * F3; i += 256) sWr[i] = Wr[i];
    for (int i = tid; i < F3; i += 256)        sWr[RBFN * F3 + i] = br[i];
    __syncthreads();

    const float4* Wr4 = (const float4*)sWr;                 // row stride 96 float4
    const float4* br4 = (const float4*)(sWr + RBFN * F3);

    const int lane = tid & 31;
    const int wid  = tid >> 5;
    float* out_s = out;
    float* out_v = out + (size_t)NNODES * FDIM;
    const float4* phi4 = (const float4*)g_phi;
    const float4* nv4  = (const float4*)nv;

    long e0 = ((long)blockIdx.x * 8 + wid) * EPW;

    for (int t = 0; t < EPW; t++) {
        long e = e0 + t;
        int2 de = eidx[e];                // .x = dst, .y = src
        float rx = rvec[3 * e + 0];
        float ry = rvec[3 * e + 1];
        float rz = rvec[3 * e + 2];
        float d  = sqrtf(rx * rx + ry * ry + rz * rz);
        if (d >= RCUT) continue;          // fcut == 0 -> zero contribution

        float inv_d = 1.0f / d;
        float fc  = 0.5f * (__cosf(d * (PI_F / RCUT)) + 1.0f);
        float hx = rx * inv_d, hy = ry * inv_d, hz = rz * inv_d;

        // lane n (0..19) owns sinc_{n+1} = sin(d*(n+1)*pi/R)/d
        // accurate sinf: argument reaches ~63 rad, MUFU error margin too thin
        float sv = sinf(d * (float)(lane + 1) * (PI_F / RCUT)) * inv_d;

        // rbf[j] for this lane's 12 outputs: j = 4*lane (+0/128/256)
        float4 rA = br4[lane];
        float4 rB = br4[32 + lane];
        float4 rC = br4[64 + lane];
        #pragma unroll
        for (int n = 0; n < RBFN; n++) {
            float s = __shfl_sync(0xffffffffu, sv, n);
            float4 wA = Wr4[n * 96 + lane];
            float4 wB = Wr4[n * 96 + 32 + lane];
            float4 wC = Wr4[n * 96 + 64 + lane];
            rA.x = fmaf(s, wA.x, rA.x); rA.y = fmaf(s, wA.y, rA.y);
            rA.z = fmaf(s, wA.z, rA.z); rA.w = fmaf(s, wA.w, rA.w);
            rB.x = fmaf(s, wB.x, rB.x); rB.y = fmaf(s, wB.y, rB.y);
            rB.z = fmaf(s, wB.z, rB.z); rB.w = fmaf(s, wB.w, rB.w);
            rC.x = fmaf(s, wC.x, rC.x); rC.y = fmaf(s, wC.y, rC.y);
            rC.z = fmaf(s, wC.z, rC.z); rC.w = fmaf(s, wC.w, rC.w);
        }

        long sb = (long)de.y * 96;        // src row, float4 units
        float4 pA = phi4[sb + lane];
        float4 pB = phi4[sb + 32 + lane];
        float4 pC = phi4[sb + 64 + lane];

        float4 s1, s2, s3;
        s1.x = pA.x * rA.x * fc; s1.y = pA.y * rA.y * fc;
        s1.z = pA.z * rA.z * fc; s1.w = pA.w * rA.w * fc;
        s2.x = pB.x * rB.x * fc; s2.y = pB.y * rB.y * fc;
        s2.z = pB.z * rB.z * fc; s2.w = pB.w * rB.w * fc;
        s3.x = pC.x * rC.x * fc; s3.y = pC.y * rC.y * fc;
        s3.z = pC.z * rC.z * fc; s3.w = pC.w * rC.w * fc;

        // node_vector[src], lane owns flat elems 12*lane .. 12*lane+11  (f=4l..4l+3, xyz)
        float4 v0 = nv4[sb + 3 * lane + 0];
        float4 v1 = nv4[sb + 3 * lane + 1];
        float4 v2 = nv4[sb + 3 * lane + 2];

        float4 m0, m1, m2;
        m0.x = fmaf(s1.x, v0.x, s3.x * hx);
        m0.y = fmaf(s1.x, v0.y, s3.x * hy);
        m0.z = fmaf(s1.x, v0.z, s3.x * hz);
        m0.w = fmaf(s1.y, v0.w, s3.y * hx);
        m1.x = fmaf(s1.y, v1.x, s3.y * hy);
        m1.y = fmaf(s1.y, v1.y, s3.y * hz);
        m1.z = fmaf(s1.z, v1.z, s3.z * hx);
        m1.w = fmaf(s1.z, v1.w, s3.z * hy);
        m2.x = fmaf(s1.z, v2.x, s3.z * hz);
        m2.y = fmaf(s1.w, v2.y, s3.w * hx);
        m2.z = fmaf(s1.w, v2.z, s3.w * hy);
        m2.w = fmaf(s1.w, v2.w, s3.w * hz);

        red4(out_s + (size_t)de.x * FDIM + 4 * lane, s2);
        float* vb = out_v + (size_t)de.x * F3 + 12 * lane;
        red4(vb + 0, m0);
        red4(vb + 4, m1);
        red4(vb + 8, m2);
    }
}

// ---------------------------------------------------------------------------
extern "C" void kernel_launch(void* const* d_in, const int* in_sizes, int n_in,
                              void* d_out, int out_size) {
    const float* ns = (const float*)d_in[0];
    const float* nv = (const float*)d_in[1];
    const float* rv = (const float*)d_in[2];
    const float* W1 = (const float*)d_in[3];
    const float* b1 = (const float*)d_in[4];
    const float* W2 = (const float*)d_in[5];
    const float* b2 = (const float*)d_in[6];
    const float* Wr = (const float*)d_in[7];
    const float* br = (const float*)d_in[8];
    const int2*  ei = (const int2*)d_in[9];
    float* out = (float*)d_out;

    cudaFuncSetAttribute(phi_kernel,
                         cudaFuncAttributeMaxDynamicSharedMemorySize, 131072);

    // 1) out = concat(node_scalar, node_vector)
    {
        int n4 = NNODES * (FDIM + F3) / 4;                 // 6,400,000
        init_out_kernel<<<(n4 + 255) / 256, 256>>>(
            (const float4*)ns, (const float4*)nv, (float4*)out);
    }
    // 2) per-node phi
    phi_kernel<<<(NNODES + 127) / 128, 256, 131072>>>(ns, W1, b1, W2, b2);
    // 3) per-edge message + scatter
    edge_kernel<<<NEDGES / (8 * EPW), 256>>>(ei, rv, Wr, br, nv, out);
}

// round 5
// speedup vs baseline: 1.1263x; 1.1263x over previous
#include <cuda_runtime.h>

#define NNODES 50000
#define NEDGES 800000
#define FDIM   128
#define F3     384
#define RBFN   20
#define RCUT   5.0f
#define PI_F   3.14159265358979f

// Scratch: per-node phi = (silu(ns@W1+b1))@W2 + b2, shape (N, 384)
__device__ float g_phi[(size_t)NNODES * F3];

// ---------------------------------------------------------------------------
// Kernel 1: out = concat(node_scalar, node_vector)  (scatter-adds land on top)
// ---------------------------------------------------------------------------
__global__ void init_out_kernel(const float4* __restrict__ ns,
                                const float4* __restrict__ nv,
                                float4* __restrict__ out) {
    int i = blockIdx.x * blockDim.x + threadIdx.x;
    const int NS4 = NNODES * FDIM / 4;          // 1,600,000
    const int NT4 = NS4 + NNODES * F3 / 4;      // 6,400,000
    if (i < NS4)       out[i] = ns[i];
    else if (i < NT4)  out[i] = nv[i - NS4];
}

// ---------------------------------------------------------------------------
// Kernel 2: per-node fused MLP.  128-row tile per block, 256 threads,
// 8x8 register micro-tile, operands in smem (Xs 64KB + Ws 64KB).
// ---------------------------------------------------------------------------
__device__ __forceinline__ void mm_tile_128(const float* __restrict__ Xs,
                                            const float* __restrict__ Ws,
                                            int r0, int tc, float acc[8][8]) {
    #pragma unroll 4
    for (int k = 0; k < 128; k++) {
        float a[8];
        #pragma unroll
        for (int i = 0; i < 8; i++) a[i] = Xs[(r0 + i) * 128 + k];
        float4 bA = ((const float4*)Ws)[k * 32 + tc * 2];
        float4 bB = ((const float4*)Ws)[k * 32 + tc * 2 + 1];
        float b[8] = {bA.x, bA.y, bA.z, bA.w, bB.x, bB.y, bB.z, bB.w};
        #pragma unroll
        for (int i = 0; i < 8; i++)
            #pragma unroll
            for (int j = 0; j < 8; j++)
                acc[i][j] = fmaf(a[i], b[j], acc[i][j]);
    }
}

__global__ __launch_bounds__(256) void phi_kernel(
        const float* __restrict__ X,
        const float* __restrict__ W1,
        const float* __restrict__ b1,
        const float* __restrict__ W2,
        const float* __restrict__ b2) {
    extern __shared__ float sm[];
    float* Xs = sm;            // 128x128 tile (X, later h)
    float* Ws = sm + 16384;    // 128x128 weight tile
    const int tid  = threadIdx.x;
    const int row0 = blockIdx.x * 128;

    {
        const float4* X4  = (const float4*)X;
        const float4* W14 = (const float4*)W1;
        float4* Xs4 = (float4*)Xs;
        float4* Ws4 = (float4*)Ws;
        #pragma unroll
        for (int t = 0; t < 16; t++) {
            int i = tid + t * 256;
            int r = i >> 5, c = i & 31;
            int gr = row0 + r;
            float4 v = make_float4(0.f, 0.f, 0.f, 0.f);
            if (gr < NNODES) v = X4[gr * 32 + c];
            Xs4[i] = v;
        }
        #pragma unroll
        for (int t = 0; t < 16; t++) {
            int i = tid + t * 256;
            Ws4[i] = W14[i];
        }
    }
    __syncthreads();

    const int tr = tid >> 4, tc = tid & 15;
    const int r0 = tr * 8,  c0 = tc * 8;

    // ---- stage 1: h = silu(X @ W1 + b1) ----
    float acc[8][8];
    #pragma unroll
    for (int i = 0; i < 8; i++)
        #pragma unroll
        for (int j = 0; j < 8; j++) acc[i][j] = 0.f;

    mm_tile_128(Xs, Ws, r0, tc, acc);
    __syncthreads();   // all reads of Xs (as X) done

    #pragma unroll
    for (int j = 0; j < 8; j++) {
        float bias = b1[c0 + j];
        #pragma unroll
        for (int i = 0; i < 8; i++) {
            float v = acc[i][j] + bias;
            Xs[(r0 + i) * 128 + c0 + j] = v / (1.f + __expf(-v));  // silu
        }
    }
    __syncthreads();   // h visible

    // ---- stage 2: phi = h @ W2 + b2, in 3 column chunks of 128 ----
    const float4* W24 = (const float4*)W2;
    for (int ch = 0; ch < 3; ch++) {
        {
            float4* Ws4 = (float4*)Ws;
            #pragma unroll
            for (int t = 0; t < 16; t++) {
                int i = tid + t * 256;
                int k = i >> 5, c = i & 31;
                Ws4[i] = W24[k * 96 + ch * 32 + c];   // W2 row stride 384
            }
        }
        __syncthreads();

        float acc2[8][8];
        #pragma unroll
        for (int i = 0; i < 8; i++)
            #pragma unroll
            for (int j = 0; j < 8; j++) acc2[i][j] = 0.f;

        mm_tile_128(Xs, Ws, r0, tc, acc2);

        float bb[8];
        #pragma unroll
        for (int j = 0; j < 8; j++) bb[j] = b2[ch * 128 + c0 + j];

        #pragma unroll
        for (int i = 0; i < 8; i++) {
            int gr = row0 + r0 + i;
            if (gr < NNODES) {
                float4 o0 = make_float4(acc2[i][0] + bb[0], acc2[i][1] + bb[1],
                                        acc2[i][2] + bb[2], acc2[i][3] + bb[3]);
                float4 o1 = make_float4(acc2[i][4] + bb[4], acc2[i][5] + bb[5],
                                        acc2[i][6] + bb[6], acc2[i][7] + bb[7]);
                float4* dst = (float4*)(g_phi + (size_t)gr * F3 + ch * 128 + c0);
                dst[0] = o0;
                dst[1] = o1;
            }
        }
        __syncthreads();   // Ws reads done before next chunk overwrites
    }
}

// ---------------------------------------------------------------------------
// Kernel 3: per-edge RBF + gather + scatter-add.
// One warp per edge-batch of EB=4 edges (register-resident), EITER batches
// per warp.  Sines via Chebyshev recurrence (no shfl, no libm sinf).
// Vector atomics (red.global.add.v4.f32).
// ---------------------------------------------------------------------------
__device__ __forceinline__ void red4(float* p, float4 v) {
    asm volatile("red.global.add.v4.f32 [%0], {%1, %2, %3, %4};"
                 :: "l"(p), "f"(v.x), "f"(v.y), "f"(v.z), "f"(v.w)
                 : "memory");
}

#define EB    4   // edges processed simultaneously per warp (register-batched)
#define EITER 2   // batches per warp  -> 8 edges per warp total

__global__ __launch_bounds__(256) void edge_kernel(
        const int2*  __restrict__ eidx,
        const float* __restrict__ rvec,
        const float* __restrict__ Wr,
        const float* __restrict__ br,
        const float* __restrict__ nv,
        float* __restrict__ out) {
    __shared__ float sWr[RBFN * F3 + F3];
    const int tid = threadIdx.x;
    for (int i = tid; i < RBFN * F3; i += 256) sWr[i] = Wr[i];
    for (int i = tid; i < F3; i += 256)        sWr[RBFN * F3 + i] = br[i];
    __syncthreads();

    const float4* Wr4 = (const float4*)sWr;                 // row stride 96 float4
    const float4* br4 = (const float4*)(sWr + RBFN * F3);

    const int lane = tid & 31;
    const int wid  = tid >> 5;
    float* out_s = out;
    float* out_v = out + (size_t)NNODES * FDIM;
    const float4* phi4 = (const float4*)g_phi;
    const float4* nv4  = (const float4*)nv;

    long e0 = ((long)blockIdx.x * 8 + wid) * (EB * EITER);

    for (int t = 0; t < EITER; t++) {
        long eb = e0 + (long)t * EB;

        // ---- phase A: per-edge geometry ----
        float fcv[EB], cth[EB], sn[EB], snm1[EB];
        float hx[EB], hy[EB], hz[EB];
        int dstv[EB], srcv[EB];
        #pragma unroll
        for (int be = 0; be < EB; be++) {
            long e = eb + be;
            int2 de = eidx[e];
            dstv[be] = de.x; srcv[be] = de.y;
            float rx = rvec[3 * e + 0];
            float ry = rvec[3 * e + 1];
            float rz = rvec[3 * e + 2];
            float d  = sqrtf(rx * rx + ry * ry + rz * rz);
            float id = 1.0f / d;
            float th = d * (PI_F / RCUT);          // < pi when active
            float c  = __cosf(th);
            fcv[be]  = (d < RCUT) ? 0.5f * (c + 1.0f) : 0.0f;
            cth[be]  = 2.0f * c;                   // recurrence coefficient
            sn[be]   = __sinf(th) * id;            // sinc_1 (inv_d folded in)
            snm1[be] = 0.0f;                       // sinc_0
            hx[be] = rx * id; hy[be] = ry * id; hz[be] = rz * id;
        }

        // ---- phase B: rbf = sinc @ Wr + br for all EB edges ----
        float4 aA[EB], aB[EB], aC[EB];
        {
            float4 bA = br4[lane], bB = br4[32 + lane], bC = br4[64 + lane];
            #pragma unroll
            for (int be = 0; be < EB; be++) { aA[be] = bA; aB[be] = bB; aC[be] = bC; }
        }
        #pragma unroll
        for (int n = 0; n < RBFN; n++) {
            float4 wA = Wr4[n * 96 + lane];
            float4 wB = Wr4[n * 96 + 32 + lane];
            float4 wC = Wr4[n * 96 + 64 + lane];
            #pragma unroll
            for (int be = 0; be < EB; be++) {
                float s = sn[be];
                aA[be].x = fmaf(s, wA.x, aA[be].x);
                aA[be].y = fmaf(s, wA.y, aA[be].y);
                aA[be].z = fmaf(s, wA.z, aA[be].z);
                aA[be].w = fmaf(s, wA.w, aA[be].w);
                aB[be].x = fmaf(s, wB.x, aB[be].x);
                aB[be].y = fmaf(s, wB.y, aB[be].y);
                aB[be].z = fmaf(s, wB.z, aB[be].z);
                aB[be].w = fmaf(s, wB.w, aB[be].w);
                aC[be].x = fmaf(s, wC.x, aC[be].x);
                aC[be].y = fmaf(s, wC.y, aC[be].y);
                aC[be].z = fmaf(s, wC.z, aC[be].z);
                aC[be].w = fmaf(s, wC.w, aC[be].w);
                // Chebyshev: sin((n+1)t) = 2cos(t) sin(nt) - sin((n-1)t)
                float nx = fmaf(cth[be], s, -snm1[be]);
                snm1[be] = s;
                sn[be]   = nx;
            }
        }

        // ---- phase C: gather phi/nv, form messages, scatter ----
        #pragma unroll
        for (int be = 0; be < EB; be++) {
            float fc = fcv[be];
            if (fc == 0.0f) continue;       // inactive edge: zero contribution

            long sb = (long)srcv[be] * 96;  // src row in float4 units
            float4 pA = phi4[sb + lane];
            float4 pB = phi4[sb + 32 + lane];
            float4 pC = phi4[sb + 64 + lane];

            float4 s1, s2, s3;
            s1.x = pA.x * aA[be].x * fc; s1.y = pA.y * aA[be].y * fc;
            s1.z = pA.z * aA[be].z * fc; s1.w = pA.w * aA[be].w * fc;
            s2.x = pB.x * aB[be].x * fc; s2.y = pB.y * aB[be].y * fc;
            s2.z = pB.z * aB[be].z * fc; s2.w = pB.w * aB[be].w * fc;
            s3.x = pC.x * aC[be].x * fc; s3.y = pC.y * aC[be].y * fc;
            s3.z = pC.z * aC[be].z * fc; s3.w = pC.w * aC[be].w * fc;

            float4 v0 = nv4[sb + 3 * lane + 0];
            float4 v1 = nv4[sb + 3 * lane + 1];
            float4 v2 = nv4[sb + 3 * lane + 2];

            float bx = hx[be], by = hy[be], bz = hz[be];
            float4 m0, m1, m2;
            m0.x = fmaf(s1.x, v0.x, s3.x * bx);
            m0.y = fmaf(s1.x, v0.y, s3.x * by);
            m0.z = fmaf(s1.x, v0.z, s3.x * bz);
            m0.w = fmaf(s1.y, v0.w, s3.y * bx);
            m1.x = fmaf(s1.y, v1.x, s3.y * by);
            m1.y = fmaf(s1.y, v1.y, s3.y * bz);
            m1.z = fmaf(s1.z, v1.z, s3.z * bx);
            m1.w = fmaf(s1.z, v1.w, s3.z * by);
            m2.x = fmaf(s1.z, v2.x, s3.z * bz);
            m2.y = fmaf(s1.w, v2.y, s3.w * bx);
            m2.z = fmaf(s1.w, v2.z, s3.w * by);
            m2.w = fmaf(s1.w, v2.w, s3.w * bz);

            red4(out_s + (size_t)dstv[be] * FDIM + 4 * lane, s2);
            float* vb = out_v + (size_t)dstv[be] * F3 + 12 * lane;
            red4(vb + 0, m0);
            red4(vb + 4, m1);
            red4(vb + 8, m2);
        }
    }
}

// ---------------------------------------------------------------------------
extern "C" void kernel_launch(void* const* d_in, const int* in_sizes, int n_in,
                              void* d_out, int out_size) {
    const float* ns = (const float*)d_in[0];
    const float* nv = (const float*)d_in[1];
    const float* rv = (const float*)d_in[2];
    const float* W1 = (const float*)d_in[3];
    const float* b1 = (const float*)d_in[4];
    const float* W2 = (const float*)d_in[5];
    const float* b2 = (const float*)d_in[6];
    const float* Wr = (const float*)d_in[7];
    const float* br = (const float*)d_in[8];
    const int2*  ei = (const int2*)d_in[9];
    float* out = (float*)d_out;

    cudaFuncSetAttribute(phi_kernel,
                         cudaFuncAttributeMaxDynamicSharedMemorySize, 131072);

    // 1) out = concat(node_scalar, node_vector)
    {
        int n4 = NNODES * (FDIM + F3) / 4;                 // 6,400,000
        init_out_kernel<<<(n4 + 255) / 256, 256>>>(
            (const float4*)ns, (const float4*)nv, (float4*)out);
    }
    // 2) per-node phi
    phi_kernel<<<(NNODES + 127) / 128, 256, 131072>>>(ns, W1, b1, W2, b2);
    // 3) per-edge message + scatter
    edge_kernel<<<NEDGES / (8 * EB * EITER), 256>>>(ei, rv, Wr, br, nv, out);
}